// round 13
// baseline (speedup 1.0000x reference)
#include <cuda_runtime.h>
#include <cuda_bf16.h>
#include <math.h>

#define BB 8192

typedef unsigned long long u64;
typedef unsigned int u32;

// ---------------- intermediate buffers (zero-init; halos stay zero = quirk zeros) ----------
__device__ float g_xT[3 * 30 * 30 * BB];     // [c][30][30][b], 28x28 valid at idx 1..28
__device__ float g_a1[8 * 14 * 14 * BB];     // layer1 out, 13x13 valid at idx 1..13
__device__ float g_bufA[16 * 14 * 14 * BB];  // ping, 12x12 valid at idx 1..12
__device__ float g_bufB[16 * 14 * 14 * BB];  // pong
__device__ float g_a6[32 * 5 * 5 * BB];      // layer6 out (compact 5x5 valid)

// pre-packed per-lane mma B-fragments (hi/lo split), one image per conv3 layer:
// layout [kstep][nhalf(2)][plane(2)][lane(32)][2 x u32]
// sizes: layer2 (K16=5): 5*1024B = 5120 ; layers3-5 (K16=9): 9216 each
__device__ __align__(16) unsigned char g_wimg[5120 + 3 * 9216 + 64];

// ---------------- f32x2 helpers (scalar layers) --------------------------------------------
__device__ __forceinline__ void fma2(u64& d, u64 a, u64 b) {
    asm("fma.rn.f32x2 %0, %1, %2, %0;" : "+l"(d) : "l"(a), "l"(b));
}
__device__ __forceinline__ u64 pack2(float lo, float hi) {
    u64 r;
    asm("mov.b64 %0, {%1, %2};" : "=l"(r) : "f"(lo), "f"(hi));
    return r;
}
__device__ __forceinline__ float2 unpack2(u64 v) {
    float2 f;
    asm("mov.b64 {%0, %1}, %2;" : "=f"(f.x), "=f"(f.y) : "l"(v));
    return f;
}
__device__ __forceinline__ u64 ldg2(const float* p) {
    return *reinterpret_cast<const u64*>(p);
}

// ---------------- mma helpers ---------------------------------------------------------------
// d{4xf32} += A{16x16 bf16} * B{16x8 bf16}   (m16n8k16, row.col)
__device__ __forceinline__ void mma16816(float* d, const u32* a, u32 b0, u32 b1) {
    asm volatile(
        "mma.sync.aligned.m16n8k16.row.col.f32.bf16.bf16.f32 "
        "{%0,%1,%2,%3}, {%4,%5,%6,%7}, {%8,%9}, {%0,%1,%2,%3};"
        : "+f"(d[0]), "+f"(d[1]), "+f"(d[2]), "+f"(d[3])
        : "r"(a[0]), "r"(a[1]), "r"(a[2]), "r"(a[3]), "r"(b0), "r"(b1));
}
// pack two floats to bf16x2: upper16 = cvt(h), lower16 = cvt(l)
__device__ __forceinline__ u32 cvt2bf(float h, float l) {
    u32 r;
    asm("cvt.rn.bf16x2.f32 %0, %1, %2;" : "=r"(r) : "f"(h), "f"(l));
    return r;
}
__device__ __forceinline__ u32 smem_to_u32(const void* p) {
    u32 a;
    asm("{ .reg .u64 t; cvta.to.shared.u64 t, %1; cvt.u32.u64 %0, t; }" : "=r"(a) : "l"(p));
    return a;
}
__device__ __forceinline__ void ldm_trans(u32* f, u32 addr) {
    asm volatile(
        "ldmatrix.sync.aligned.m8n8.x4.trans.shared.b16 {%0,%1,%2,%3}, [%4];"
        : "=r"(f[0]), "=r"(f[1]), "=r"(f[2]), "=r"(f[3])
        : "r"(addr));
}

// ---------------- transpose: x (B, 3*28*28) NCHW -> padded xT [c][30][30][B] ---------------
__global__ void __launch_bounds__(256) transpose_kernel(const float* __restrict__ x) {
    __shared__ float tile[32][33];
    int p0 = blockIdx.x * 32;
    int b0 = blockIdx.y * 32;
    int tx = threadIdx.x, ty = threadIdx.y;  // (32, 8)
#pragma unroll
    for (int j = 0; j < 4; j++) {
        int p = p0 + tx;
        int bb = b0 + ty + 8 * j;
        tile[ty + 8 * j][tx] = (p < 2352) ? x[bb * 2352 + p] : 0.f;
    }
    __syncthreads();
#pragma unroll
    for (int j = 0; j < 4; j++) {
        int p = p0 + ty + 8 * j;
        int bb = b0 + tx;
        if (p < 2352) {
            int c = p / 784, rem = p % 784;
            int h = rem / 28, w = rem % 28;
            g_xT[((c * 30 + h + 1) * 30 + (w + 1)) * BB + bb] = tile[tx][ty + 8 * j];
        }
    }
}

// ---------------- layer 1 (scalar, from R8) -------------------------------------------------
template <int OWG>
__device__ __forceinline__ void conv1_body(const u64* __restrict__ ws2, int ow0, int b, int oh) {
    constexpr int S = 2 * OWG + 3;
    u64 acc[8][OWG];
#pragma unroll
    for (int co = 0; co < 8; co++)
#pragma unroll
        for (int ow = 0; ow < OWG; ow++) acc[co][ow] = 0ULL;

#pragma unroll 1
    for (int ci = 0; ci < 3; ci++) {
#pragma unroll
        for (int kh = 0; kh < 5; kh++) {
            const float* rowp = g_xT + ((ci * 30 + 2 * oh + kh) * 30 + 2 * ow0) * BB + b;
            u64 r[S];
#pragma unroll
            for (int j = 0; j < S; j++) r[j] = ldg2(rowp + j * BB);
#pragma unroll
            for (int kw = 0; kw < 5; kw++) {
                int base = ((ci * 5 + kh) * 5 + kw) * 8;
                ulonglong2 w01 = *reinterpret_cast<const ulonglong2*>(ws2 + base);
                ulonglong2 w23 = *reinterpret_cast<const ulonglong2*>(ws2 + base + 2);
                ulonglong2 w45 = *reinterpret_cast<const ulonglong2*>(ws2 + base + 4);
                ulonglong2 w67 = *reinterpret_cast<const ulonglong2*>(ws2 + base + 6);
#pragma unroll
                for (int ow = 0; ow < OWG; ow++) {
                    u64 v = r[2 * ow + kw];
                    fma2(acc[0][ow], v, w01.x);
                    fma2(acc[1][ow], v, w01.y);
                    fma2(acc[2][ow], v, w23.x);
                    fma2(acc[3][ow], v, w23.y);
                    fma2(acc[4][ow], v, w45.x);
                    fma2(acc[5][ow], v, w45.y);
                    fma2(acc[6][ow], v, w67.x);
                    fma2(acc[7][ow], v, w67.y);
                }
            }
        }
    }
#pragma unroll
    for (int co = 0; co < 8; co++)
#pragma unroll
        for (int ow = 0; ow < OWG; ow++) {
            float2 v = unpack2(acc[co][ow]);
            float2 o;
            o.x = fmaxf(v.x, 0.f);
            o.y = fmaxf(v.y, 0.f);
            *reinterpret_cast<float2*>(g_a1 + ((co * 14 + oh + 1) * 14 + ow0 + ow + 1) * BB + b) =
                o;
        }
}

__global__ void __launch_bounds__(96) conv1_kernel(const float* __restrict__ Kw) {
    __shared__ __align__(16) u64 ws2[600];
    int tid = threadIdx.y * 32 + threadIdx.x;
    for (int i = tid; i < 600; i += 96) {
        float w = Kw[i];
        ws2[i] = pack2(w, w);
    }
    __syncthreads();
    int b = blockIdx.x * 64 + threadIdx.x * 2;
    int oh = blockIdx.y;
    int ty = threadIdx.y;
    if (ty == 0) conv1_body<4>(ws2, 0, b, oh);
    else if (ty == 1) conv1_body<4>(ws2, 4, b, oh);
    else conv1_body<5>(ws2, 8, b, oh);
}

// ---------------- weight prep: per-lane mma B-fragments, hi/lo bf16 split ------------------
// B[k][n] = Kflat[k*16 + n] (flatten-order quirk), zero-padded for k >= K.
__global__ void __launch_bounds__(512) prep_weights(const float* __restrict__ K2,
                                                    const float* __restrict__ K3,
                                                    const float* __restrict__ K4,
                                                    const float* __restrict__ K5) {
    int l = blockIdx.x;
    const float* W = (l == 0) ? K2 : (l == 1) ? K3 : (l == 2) ? K4 : K5;
    int K = (l == 0) ? 72 : 144;
    int K16 = (l == 0) ? 5 : 9;
    u32* img = reinterpret_cast<u32*>(g_wimg + ((l == 0) ? 0 : 5120 + (l - 1) * 9216));
    int items = K16 * 2 * 2 * 32;  // (s, h, p, lane)
    for (int i = threadIdx.x; i < items; i += 512) {
        int lane = i & 31;
        int p = (i >> 5) & 1;
        int h = (i >> 6) & 1;
        int s = i >> 7;
        int g = lane >> 2, tig = lane & 3;
        int n = h * 8 + g;
        int kk[4] = {s * 16 + tig * 2, s * 16 + tig * 2 + 1, s * 16 + tig * 2 + 8,
                     s * 16 + tig * 2 + 9};
        unsigned short hs[4];
#pragma unroll
        for (int j = 0; j < 4; j++) {
            float v = (kk[j] < K) ? W[kk[j] * 16 + n] : 0.f;
            __nv_bfloat16 hb = __float2bfloat16(v);
            if (p == 0) {
                hs[j] = __bfloat16_as_ushort(hb);
            } else {
                __nv_bfloat16 lb = __float2bfloat16(v - __bfloat162float(hb));
                hs[j] = __bfloat16_as_ushort(lb);
            }
        }
        img[i * 2] = (u32)hs[0] | ((u32)hs[1] << 16);
        img[i * 2 + 1] = (u32)hs[2] | ((u32)hs[3] << 16);
    }
}

// ---------------- conv3 via mma.sync bf16, smem-staged A + ldmatrix.trans ------------------
__device__ __forceinline__ float* buf_ptr(int id) {
    return id == 0 ? g_a1 : (id == 1 ? g_bufA : g_bufB);
}

template <int CIN, int SRC, int DST, int WOFF>
__global__ void __launch_bounds__(128) conv3_mma_kernel() {
    constexpr int K = CIN * 9;
    constexpr int K16 = (K + 15) / 16;
    constexpr int NFRAG = K16 * 256;  // u32: [s][nh 2][plane 2][lane 32][2]

    __shared__ __align__(16) u32 sBF[NFRAG];
    // A tile: [buf 2][plane 2][16 k x 72 b (pad)] bf16 ; row = 144B (9x16B, conflict-free)
    __shared__ __align__(16) unsigned short sA[2][2][16 * 72];
    __shared__ int koff[K16 * 16];

    int tid = threadIdx.x;
    {
        const uint4* src = reinterpret_cast<const uint4*>(g_wimg + WOFF);
        for (int i = tid; i < NFRAG / 4; i += 128)
            reinterpret_cast<uint4*>(sBF)[i] = src[i];
        for (int i = tid; i < K16 * 16; i += 128)
            koff[i] = (i < K) ? ((i / 9) * 196 + ((i % 9) / 3) * 14 + (i % 3)) : 0;
    }

    int lane = tid & 31;
    int w = tid >> 5;
    int tig = lane & 3;
    int g = lane >> 2;
    int bb = blockIdx.x * 64;
    int bw = w * 16;  // warp's batch offset within the 64-wide block tile
    int oh = blockIdx.y / 12, ow = blockIdx.y % 12;
    const float* base = buf_ptr(SRC) + (oh * 14 + ow) * BB + bb;  // padded top-left tap
    float* out = buf_ptr(DST);

    // per-lane ldmatrix row offset (u16 units): k row + b col of the stored [k][b] tile
    int k_l = (lane & 7) + ((lane & 16) >> 1);
    int b_l = bw + (lane & 8);
    u32 sA0 = smem_to_u32(sA);
    u32 lm_byte = (u32)((k_l * 72 + b_l) * 2);

    __syncthreads();  // koff ready before staging uses it

    // ---- stage kstep s into buffer bi: 16 k-rows x 64 b, coalesced float2, split hi/lo ----
    auto stage = [&](int s, int bi) {
#pragma unroll
        for (int j = 0; j < 4; j++) {
            int idx = j * 128 + tid;  // 0..511 float2 units
            int k = idx >> 5;
            int c = idx & 31;
            const float2 v2 =
                *reinterpret_cast<const float2*>(base + koff[s * 16 + k] * BB + 2 * c);
            u32 hi = cvt2bf(v2.y, v2.x);
            float l0 = v2.x - __uint_as_float(hi << 16);
            float l1 = v2.y - __uint_as_float(hi & 0xffff0000u);
            u32 lo = cvt2bf(l1, l0);
            reinterpret_cast<u32*>(sA[bi][0])[k * 36 + c] = hi;
            reinterpret_cast<u32*>(sA[bi][1])[k * 36 + c] = lo;
        }
    };

    float d[2][4] = {{0.f, 0.f, 0.f, 0.f}, {0.f, 0.f, 0.f, 0.f}};

    stage(0, 0);
    __syncthreads();
#pragma unroll 1
    for (int s = 0; s < K16; s++) {
        int bi = s & 1;
        u32 ha[4], la[4];
        ldm_trans(ha, sA0 + (u32)(bi * 2 + 0) * 2304u + lm_byte);
        ldm_trans(la, sA0 + (u32)(bi * 2 + 1) * 2304u + lm_byte);
#pragma unroll
        for (int nh = 0; nh < 2; nh++) {
            const u32* fb = sBF + (((s * 2 + nh) * 2) * 32 + lane) * 2;
            u32 bh0 = fb[0], bh1 = fb[1];    // hi plane
            u32 bl0 = fb[64], bl1 = fb[65];  // lo plane
            mma16816(d[nh], ha, bh0, bh1);   // Ah * Bh
            mma16816(d[nh], la, bh0, bh1);   // Al * Bh
            mma16816(d[nh], ha, bl0, bl1);   // Ah * Bl
        }
        if (s + 1 < K16) stage(s + 1, bi ^ 1);
        __syncthreads();
    }

    // epilogue: ReLU + fp32 store to padded [co][14][14][B]
    float* outp = out + ((oh + 1) * 14 + (ow + 1)) * BB + bb + bw;
#pragma unroll
    for (int nh = 0; nh < 2; nh++)
#pragma unroll
        for (int j = 0; j < 4; j++) {
            int co = nh * 8 + tig * 2 + (j & 1);
            int r = g + ((j >> 1) << 3);
            outp[co * 196 * BB + r] = fmaxf(d[nh][j], 0.f);
        }
}

// ---------------- layer 6 (scalar, from R8) -------------------------------------------------
__global__ void __launch_bounds__(256, 2) conv6_kernel(const float* __restrict__ Kw) {
    __shared__ __align__(16) u64 ws2[3200];
    int tid = threadIdx.y * 32 + threadIdx.x;
    int co0 = threadIdx.y * 4;
    int b = blockIdx.x * 64 + threadIdx.x * 2;
    int oh = blockIdx.y;

    u64 acc[4][5];
#pragma unroll
    for (int co = 0; co < 4; co++)
#pragma unroll
        for (int ow = 0; ow < 5; ow++) acc[co][ow] = 0ULL;

#pragma unroll 1
    for (int cc = 0; cc < 4; cc++) {
        if (cc > 0) __syncthreads();
        for (int i = tid; i < 3200; i += 256) {
            float w = Kw[cc * 3200 + i];
            ws2[i] = pack2(w, w);
        }
        __syncthreads();
#pragma unroll 1
        for (int c4 = 0; c4 < 4; c4++) {
            int ci = cc * 4 + c4;
#pragma unroll
            for (int kh = 0; kh < 5; kh++) {
                const float* rowp = g_bufB + ((ci * 14 + 2 * oh + kh) * 14) * BB + b;
                u64 r[13];
#pragma unroll
                for (int j = 0; j < 13; j++) r[j] = ldg2(rowp + j * BB);
#pragma unroll
                for (int kw = 0; kw < 5; kw++) {
                    int base = (c4 * 25 + kh * 5 + kw) * 32 + co0;
                    ulonglong2 w01 = *reinterpret_cast<const ulonglong2*>(ws2 + base);
                    ulonglong2 w23 = *reinterpret_cast<const ulonglong2*>(ws2 + base + 2);
#pragma unroll
                    for (int ow = 0; ow < 5; ow++) {
                        u64 v = r[2 * ow + kw];
                        fma2(acc[0][ow], v, w01.x);
                        fma2(acc[1][ow], v, w01.y);
                        fma2(acc[2][ow], v, w23.x);
                        fma2(acc[3][ow], v, w23.y);
                    }
                }
            }
        }
    }
#pragma unroll
    for (int co = 0; co < 4; co++)
#pragma unroll
        for (int ow = 0; ow < 5; ow++) {
            float2 v = unpack2(acc[co][ow]);
            *reinterpret_cast<float2*>(g_a6 + (((co0 + co) * 5 + oh) * 5 + ow) * BB + b) = v;
        }
}

// ---------------- FC (1152->10, only 800 nonzero inputs) + softmax -------------------------
__global__ void __launch_bounds__(256) fc_kernel(const float* __restrict__ Wfc,
                                                 const float* __restrict__ bfc,
                                                 float* __restrict__ out) {
    __shared__ __align__(16) float Wp[8000];
    __shared__ float red[4][64][10];
    int tid = threadIdx.x;
    for (int i = tid; i < 8000; i += 256) {
        int kp = i / 10, cls = i % 10;
        int co = kp / 25, rem = kp % 25, r = rem / 5, c = rem % 5;
        Wp[i] = Wfc[cls * 1152 + co * 36 + r * 6 + c];
    }
    __syncthreads();
    const u64* Wp2 = reinterpret_cast<const u64*>(Wp);

    int bsub = tid & 63;
    int g = tid >> 6;
    int b = blockIdx.x * 64 + bsub;

    u64 lg[5] = {0ULL, 0ULL, 0ULL, 0ULL, 0ULL};
    int k0 = g * 200;
#pragma unroll 4
    for (int kp = k0; kp < k0 + 200; kp++) {
        float v = g_a6[kp * BB + b];
        u64 v2 = pack2(v, v);
#pragma unroll
        for (int c = 0; c < 5; c++) fma2(lg[c], v2, Wp2[kp * 5 + c]);
    }
#pragma unroll
    for (int c = 0; c < 5; c++) {
        float2 f = unpack2(lg[c]);
        red[g][bsub][2 * c] = f.x;
        red[g][bsub][2 * c + 1] = f.y;
    }
    __syncthreads();
    if (g == 0) {
        float logits[10];
#pragma unroll
        for (int c = 0; c < 10; c++)
            logits[c] = red[0][bsub][c] + red[1][bsub][c] + red[2][bsub][c] + red[3][bsub][c] +
                        bfc[c];
        float m = logits[0];
#pragma unroll
        for (int c = 1; c < 10; c++) m = fmaxf(m, logits[c]);
        float s = 0.f;
#pragma unroll
        for (int c = 0; c < 10; c++) {
            float e = expf(logits[c] - m);
            logits[c] = e;
            s += e;
        }
        float inv = 1.f / s;
#pragma unroll
        for (int c = 0; c < 10; c++) out[b * 10 + c] = logits[c] * inv;
    }
}

// ---------------- launch -------------------------------------------------------------------
extern "C" void kernel_launch(void* const* d_in, const int* in_sizes, int n_in, void* d_out,
                              int out_size) {
    const float* x = (const float*)d_in[0];
    const float* K1 = (const float*)d_in[1];
    const float* K2 = (const float*)d_in[2];
    const float* K3 = (const float*)d_in[3];
    const float* K4 = (const float*)d_in[4];
    const float* K5 = (const float*)d_in[5];
    const float* K6 = (const float*)d_in[6];
    const float* Wfc = (const float*)d_in[7];
    const float* bfc = (const float*)d_in[8];
    float* out = (float*)d_out;

    prep_weights<<<4, 512>>>(K2, K3, K4, K5);
    transpose_kernel<<<dim3(74, 256), dim3(32, 8)>>>(x);
    conv1_kernel<<<dim3(128, 13), dim3(32, 3)>>>(K1);
    conv3_mma_kernel<8, 0, 1, 0><<<dim3(128, 144), 128>>>();      // a1   -> bufA (K2)
    conv3_mma_kernel<16, 1, 2, 5120><<<dim3(128, 144), 128>>>();  // bufA -> bufB (K3)
    conv3_mma_kernel<16, 2, 1, 14336><<<dim3(128, 144), 128>>>(); // bufB -> bufA (K4)
    conv3_mma_kernel<16, 1, 2, 23552><<<dim3(128, 144), 128>>>(); // bufA -> bufB (K5)
    conv6_kernel<<<dim3(128, 5), dim3(32, 8)>>>(K6);              // bufB -> a6
    fc_kernel<<<128, 256>>>(Wfc, bfc, out);
}

// round 14
// speedup vs baseline: 1.1927x; 1.1927x over previous
#include <cuda_runtime.h>
#include <cuda_bf16.h>
#include <math.h>

#define BB 8192

typedef unsigned long long u64;
typedef unsigned int u32;
typedef unsigned short u16;

// ---------------- intermediate buffers (zero-init; halos stay zero = quirk zeros) ----------
__device__ float g_xT[3 * 30 * 30 * BB];  // [c][30][30][b], 28x28 valid at idx 1..28
// bf16 hi/lo activation planes for MMA layers, padded [c][14][14][B]
__device__ u16 g_a1h[8 * 196 * BB], g_a1l[8 * 196 * BB];    // conv1 out
__device__ u16 g_pAh[16 * 196 * BB], g_pAl[16 * 196 * BB];  // ping planes
__device__ u16 g_pBh[16 * 196 * BB], g_pBl[16 * 196 * BB];  // pong planes
__device__ float g_bufB[16 * 196 * BB];                     // K5 out fp32 (for scalar conv6)
__device__ float g_a6[32 * 5 * 5 * BB];                     // layer6 out (compact 5x5)

// pre-packed per-lane mma B-fragments (hi/lo split), one image per conv3 layer:
// layout [kstep][nhalf(2)][plane(2)][lane(32)][2 x u32]
__device__ __align__(16) unsigned char g_wimg[5120 + 3 * 9216 + 64];

// ---------------- f32x2 helpers (scalar layers) --------------------------------------------
__device__ __forceinline__ void fma2(u64& d, u64 a, u64 b) {
    asm("fma.rn.f32x2 %0, %1, %2, %0;" : "+l"(d) : "l"(a), "l"(b));
}
__device__ __forceinline__ u64 pack2(float lo, float hi) {
    u64 r;
    asm("mov.b64 %0, {%1, %2};" : "=l"(r) : "f"(lo), "f"(hi));
    return r;
}
__device__ __forceinline__ float2 unpack2(u64 v) {
    float2 f;
    asm("mov.b64 {%0, %1}, %2;" : "=f"(f.x), "=f"(f.y) : "l"(v));
    return f;
}
__device__ __forceinline__ u64 ldg2(const float* p) {
    return *reinterpret_cast<const u64*>(p);
}

// ---------------- mma helpers ---------------------------------------------------------------
__device__ __forceinline__ void mma16816(float* d, const u32* a, u32 b0, u32 b1) {
    asm volatile(
        "mma.sync.aligned.m16n8k16.row.col.f32.bf16.bf16.f32 "
        "{%0,%1,%2,%3}, {%4,%5,%6,%7}, {%8,%9}, {%0,%1,%2,%3};"
        : "+f"(d[0]), "+f"(d[1]), "+f"(d[2]), "+f"(d[3])
        : "r"(a[0]), "r"(a[1]), "r"(a[2]), "r"(a[3]), "r"(b0), "r"(b1));
}
// pack two floats to bf16x2: upper16 = cvt(h), lower16 = cvt(l)
__device__ __forceinline__ u32 cvt2bf(float h, float l) {
    u32 r;
    asm("cvt.rn.bf16x2.f32 %0, %1, %2;" : "=r"(r) : "f"(h), "f"(l));
    return r;
}
__device__ __forceinline__ u32 smem_to_u32(const void* p) {
    u32 a;
    asm("{ .reg .u64 t; cvta.to.shared.u64 t, %1; cvt.u32.u64 %0, t; }" : "=r"(a) : "l"(p));
    return a;
}
__device__ __forceinline__ void ldm_trans(u32* f, u32 addr) {
    asm volatile(
        "ldmatrix.sync.aligned.m8n8.x4.trans.shared.b16 {%0,%1,%2,%3}, [%4];"
        : "=r"(f[0]), "=r"(f[1]), "=r"(f[2]), "=r"(f[3])
        : "r"(addr));
}

// ---------------- transpose: x (B, 3*28*28) NCHW -> padded xT [c][30][30][B] ---------------
__global__ void __launch_bounds__(256) transpose_kernel(const float* __restrict__ x) {
    __shared__ float tile[32][33];
    int p0 = blockIdx.x * 32;
    int b0 = blockIdx.y * 32;
    int tx = threadIdx.x, ty = threadIdx.y;  // (32, 8)
#pragma unroll
    for (int j = 0; j < 4; j++) {
        int p = p0 + tx;
        int bb = b0 + ty + 8 * j;
        tile[ty + 8 * j][tx] = (p < 2352) ? x[bb * 2352 + p] : 0.f;
    }
    __syncthreads();
#pragma unroll
    for (int j = 0; j < 4; j++) {
        int p = p0 + ty + 8 * j;
        int bb = b0 + tx;
        if (p < 2352) {
            int c = p / 784, rem = p % 784;
            int h = rem / 28, w = rem % 28;
            g_xT[((c * 30 + h + 1) * 30 + (w + 1)) * BB + bb] = tile[tx][ty + 8 * j];
        }
    }
}

// ---------------- layer 1 (scalar compute; epilogue -> bf16 hi/lo planes) ------------------
template <int OWG>
__device__ __forceinline__ void conv1_body(const u64* __restrict__ ws2, int ow0, int b, int oh) {
    constexpr int S = 2 * OWG + 3;
    u64 acc[8][OWG];
#pragma unroll
    for (int co = 0; co < 8; co++)
#pragma unroll
        for (int ow = 0; ow < OWG; ow++) acc[co][ow] = 0ULL;

#pragma unroll 1
    for (int ci = 0; ci < 3; ci++) {
#pragma unroll
        for (int kh = 0; kh < 5; kh++) {
            const float* rowp = g_xT + ((ci * 30 + 2 * oh + kh) * 30 + 2 * ow0) * BB + b;
            u64 r[S];
#pragma unroll
            for (int j = 0; j < S; j++) r[j] = ldg2(rowp + j * BB);
#pragma unroll
            for (int kw = 0; kw < 5; kw++) {
                int base = ((ci * 5 + kh) * 5 + kw) * 8;
                ulonglong2 w01 = *reinterpret_cast<const ulonglong2*>(ws2 + base);
                ulonglong2 w23 = *reinterpret_cast<const ulonglong2*>(ws2 + base + 2);
                ulonglong2 w45 = *reinterpret_cast<const ulonglong2*>(ws2 + base + 4);
                ulonglong2 w67 = *reinterpret_cast<const ulonglong2*>(ws2 + base + 6);
#pragma unroll
                for (int ow = 0; ow < OWG; ow++) {
                    u64 v = r[2 * ow + kw];
                    fma2(acc[0][ow], v, w01.x);
                    fma2(acc[1][ow], v, w01.y);
                    fma2(acc[2][ow], v, w23.x);
                    fma2(acc[3][ow], v, w23.y);
                    fma2(acc[4][ow], v, w45.x);
                    fma2(acc[5][ow], v, w45.y);
                    fma2(acc[6][ow], v, w67.x);
                    fma2(acc[7][ow], v, w67.y);
                }
            }
        }
    }
#pragma unroll
    for (int co = 0; co < 8; co++)
#pragma unroll
        for (int ow = 0; ow < OWG; ow++) {
            float2 v = unpack2(acc[co][ow]);
            float r0 = fmaxf(v.x, 0.f), r1 = fmaxf(v.y, 0.f);
            u32 hw = cvt2bf(r1, r0);
            float l0 = r0 - __uint_as_float(hw << 16);
            float l1 = r1 - __uint_as_float(hw & 0xffff0000u);
            u32 lw = cvt2bf(l1, l0);
            int idx = (co * 14 + oh + 1) * 14 + ow0 + ow + 1;
            *reinterpret_cast<u32*>(g_a1h + idx * BB + b) = hw;
            *reinterpret_cast<u32*>(g_a1l + idx * BB + b) = lw;
        }
}

__global__ void __launch_bounds__(96) conv1_kernel(const float* __restrict__ Kw) {
    __shared__ __align__(16) u64 ws2[600];
    int tid = threadIdx.y * 32 + threadIdx.x;
    for (int i = tid; i < 600; i += 96) {
        float w = Kw[i];
        ws2[i] = pack2(w, w);
    }
    __syncthreads();
    int b = blockIdx.x * 64 + threadIdx.x * 2;
    int oh = blockIdx.y;
    int ty = threadIdx.y;
    if (ty == 0) conv1_body<4>(ws2, 0, b, oh);
    else if (ty == 1) conv1_body<4>(ws2, 4, b, oh);
    else conv1_body<5>(ws2, 8, b, oh);
}

// ---------------- weight prep: per-lane mma B-fragments, hi/lo bf16 split ------------------
__global__ void __launch_bounds__(512) prep_weights(const float* __restrict__ K2,
                                                    const float* __restrict__ K3,
                                                    const float* __restrict__ K4,
                                                    const float* __restrict__ K5) {
    int l = blockIdx.x;
    const float* W = (l == 0) ? K2 : (l == 1) ? K3 : (l == 2) ? K4 : K5;
    int K = (l == 0) ? 72 : 144;
    int K16 = (l == 0) ? 5 : 9;
    u32* img = reinterpret_cast<u32*>(g_wimg + ((l == 0) ? 0 : 5120 + (l - 1) * 9216));
    int items = K16 * 2 * 2 * 32;  // (s, h, p, lane)
    for (int i = threadIdx.x; i < items; i += 512) {
        int lane = i & 31;
        int p = (i >> 5) & 1;
        int h = (i >> 6) & 1;
        int s = i >> 7;
        int g = lane >> 2, tig = lane & 3;
        int n = h * 8 + g;
        int kk[4] = {s * 16 + tig * 2, s * 16 + tig * 2 + 1, s * 16 + tig * 2 + 8,
                     s * 16 + tig * 2 + 9};
        u16 hs[4];
#pragma unroll
        for (int j = 0; j < 4; j++) {
            float v = (kk[j] < K) ? W[kk[j] * 16 + n] : 0.f;
            __nv_bfloat16 hb = __float2bfloat16(v);
            if (p == 0) {
                hs[j] = __bfloat16_as_ushort(hb);
            } else {
                __nv_bfloat16 lb = __float2bfloat16(v - __bfloat162float(hb));
                hs[j] = __bfloat16_as_ushort(lb);
            }
        }
        img[i * 2] = (u32)hs[0] | ((u32)hs[1] << 16);
        img[i * 2 + 1] = (u32)hs[2] | ((u32)hs[3] << 16);
    }
}

// ---------------- conv3 via mma.sync bf16, plane-staged A + ldmatrix.trans ------------------
// SRC: 0 = a1 planes, 1 = ping planes, 2 = pong planes
// DST: 1 = ping planes, 2 = pong planes, 3 = fp32 g_bufB (for conv6)
template <int CIN, int SRC, int DST, int WOFF>
__global__ void __launch_bounds__(128) conv3_mma_kernel() {
    constexpr int K = CIN * 9;
    constexpr int K16 = (K + 15) / 16;
    constexpr int NFRAG = K16 * 256;  // u32: [s][nh 2][plane 2][lane 32][2]

    __shared__ __align__(16) u32 sBF[NFRAG];
    // A tile: [buf 2][plane 2][16 k x 72 b(pad)] u16 ; row = 144B (9x16B, conflict-free)
    __shared__ __align__(16) u16 sA[2][2][16 * 72];
    __shared__ int koff[K16 * 16];

    const u16* srch = (SRC == 0) ? g_a1h : (SRC == 1) ? g_pAh : g_pBh;
    const u16* srcl = (SRC == 0) ? g_a1l : (SRC == 1) ? g_pAl : g_pBl;

    int tid = threadIdx.x;
    {
        const uint4* src = reinterpret_cast<const uint4*>(g_wimg + WOFF);
        for (int i = tid; i < NFRAG / 4; i += 128)
            reinterpret_cast<uint4*>(sBF)[i] = src[i];
        for (int i = tid; i < K16 * 16; i += 128)
            koff[i] = (i < K) ? ((i / 9) * 196 + ((i % 9) / 3) * 14 + (i % 3)) : 0;
    }

    int lane = tid & 31;
    int w = tid >> 5;
    int tig = lane & 3;
    int g = lane >> 2;
    int bb = blockIdx.x * 64;
    int bw = w * 16;
    int oh = blockIdx.y / 12, ow = blockIdx.y % 12;
    int tap = (oh * 14 + ow) * BB + bb;  // padded top-left tap (u16 index)

    // stage thread mapping: one (k, x) chunk, both planes
    int sk = tid >> 3, sx = tid & 7;

    // ldmatrix per-lane row address
    int k_l = (lane & 7) + ((lane & 16) >> 1);
    int b_l = bw + (lane & 8);
    u32 sA0 = smem_to_u32(sA);
    u32 lm_byte = (u32)((k_l * 72 + b_l) * 2);

    __syncthreads();  // koff/sBF ready

    auto stage = [&](int s, int bi) {
        int off = koff[s * 16 + sk] * BB + tap;
        uint4 vh = reinterpret_cast<const uint4*>(srch + off)[sx];
        uint4 vl = reinterpret_cast<const uint4*>(srcl + off)[sx];
        reinterpret_cast<uint4*>(&sA[bi][0][sk * 72])[sx] = vh;
        reinterpret_cast<uint4*>(&sA[bi][1][sk * 72])[sx] = vl;
    };

    float d[2][4] = {{0.f, 0.f, 0.f, 0.f}, {0.f, 0.f, 0.f, 0.f}};

    stage(0, 0);
    __syncthreads();
#pragma unroll 1
    for (int s = 0; s < K16; s++) {
        int bi = s & 1;
        u32 ha[4], la[4];
        ldm_trans(ha, sA0 + (u32)(bi * 2 + 0) * 2304u + lm_byte);
        ldm_trans(la, sA0 + (u32)(bi * 2 + 1) * 2304u + lm_byte);
        if (s + 1 < K16) stage(s + 1, bi ^ 1);
#pragma unroll
        for (int nh = 0; nh < 2; nh++) {
            const u32* fb = sBF + (((s * 2 + nh) * 2) * 32 + lane) * 2;
            u32 bh0 = fb[0], bh1 = fb[1];    // hi plane
            u32 bl0 = fb[64], bl1 = fb[65];  // lo plane
            mma16816(d[nh], ha, bh0, bh1);   // Ah * Bh
            mma16816(d[nh], la, bh0, bh1);   // Al * Bh
            mma16816(d[nh], ha, bl0, bl1);   // Ah * Bl
        }
        __syncthreads();
    }

    // epilogue: ReLU; write either bf16 hi/lo planes or fp32 (for conv6)
    int obase = ((oh + 1) * 14 + (ow + 1)) * BB + bb + bw;
    if (DST == 3) {
        float* outp = g_bufB + obase;
#pragma unroll
        for (int nh = 0; nh < 2; nh++)
#pragma unroll
            for (int j = 0; j < 4; j++) {
                int co = nh * 8 + tig * 2 + (j & 1);
                int r = g + ((j >> 1) << 3);
                outp[co * 196 * BB + r] = fmaxf(d[nh][j], 0.f);
            }
    } else {
        u16* dh = ((DST == 1) ? g_pAh : g_pBh) + obase;
        u16* dl = ((DST == 1) ? g_pAl : g_pBl) + obase;
#pragma unroll
        for (int nh = 0; nh < 2; nh++)
#pragma unroll
            for (int j = 0; j < 4; j++) {
                int co = nh * 8 + tig * 2 + (j & 1);
                int r = g + ((j >> 1) << 3);
                float rv = fmaxf(d[nh][j], 0.f);
                __nv_bfloat16 hb = __float2bfloat16(rv);
                float lo = rv - __bfloat162float(hb);
                dh[co * 196 * BB + r] = __bfloat16_as_ushort(hb);
                dl[co * 196 * BB + r] = __bfloat16_as_ushort(__float2bfloat16(lo));
            }
    }
}

// ---------------- layer 6 (scalar, reads fp32 g_bufB; from R8) ------------------------------
__global__ void __launch_bounds__(256, 2) conv6_kernel(const float* __restrict__ Kw) {
    __shared__ __align__(16) u64 ws2[3200];
    int tid = threadIdx.y * 32 + threadIdx.x;
    int co0 = threadIdx.y * 4;
    int b = blockIdx.x * 64 + threadIdx.x * 2;
    int oh = blockIdx.y;

    u64 acc[4][5];
#pragma unroll
    for (int co = 0; co < 4; co++)
#pragma unroll
        for (int ow = 0; ow < 5; ow++) acc[co][ow] = 0ULL;

#pragma unroll 1
    for (int cc = 0; cc < 4; cc++) {
        if (cc > 0) __syncthreads();
        for (int i = tid; i < 3200; i += 256) {
            float w = Kw[cc * 3200 + i];
            ws2[i] = pack2(w, w);
        }
        __syncthreads();
#pragma unroll 1
        for (int c4 = 0; c4 < 4; c4++) {
            int ci = cc * 4 + c4;
#pragma unroll
            for (int kh = 0; kh < 5; kh++) {
                const float* rowp = g_bufB + ((ci * 14 + 2 * oh + kh) * 14) * BB + b;
                u64 r[13];
#pragma unroll
                for (int j = 0; j < 13; j++) r[j] = ldg2(rowp + j * BB);
#pragma unroll
                for (int kw = 0; kw < 5; kw++) {
                    int base = (c4 * 25 + kh * 5 + kw) * 32 + co0;
                    ulonglong2 w01 = *reinterpret_cast<const ulonglong2*>(ws2 + base);
                    ulonglong2 w23 = *reinterpret_cast<const ulonglong2*>(ws2 + base + 2);
#pragma unroll
                    for (int ow = 0; ow < 5; ow++) {
                        u64 v = r[2 * ow + kw];
                        fma2(acc[0][ow], v, w01.x);
                        fma2(acc[1][ow], v, w01.y);
                        fma2(acc[2][ow], v, w23.x);
                        fma2(acc[3][ow], v, w23.y);
                    }
                }
            }
        }
    }
#pragma unroll
    for (int co = 0; co < 4; co++)
#pragma unroll
        for (int ow = 0; ow < 5; ow++) {
            float2 v = unpack2(acc[co][ow]);
            *reinterpret_cast<float2*>(g_a6 + (((co0 + co) * 5 + oh) * 5 + ow) * BB + b) = v;
        }
}

// ---------------- FC (1152->10, only 800 nonzero inputs) + softmax -------------------------
__global__ void __launch_bounds__(256) fc_kernel(const float* __restrict__ Wfc,
                                                 const float* __restrict__ bfc,
                                                 float* __restrict__ out) {
    __shared__ __align__(16) float Wp[8000];
    __shared__ float red[4][64][10];
    int tid = threadIdx.x;
    for (int i = tid; i < 8000; i += 256) {
        int kp = i / 10, cls = i % 10;
        int co = kp / 25, rem = kp % 25, r = rem / 5, c = rem % 5;
        Wp[i] = Wfc[cls * 1152 + co * 36 + r * 6 + c];
    }
    __syncthreads();
    const u64* Wp2 = reinterpret_cast<const u64*>(Wp);

    int bsub = tid & 63;
    int g = tid >> 6;
    int b = blockIdx.x * 64 + bsub;

    u64 lg[5] = {0ULL, 0ULL, 0ULL, 0ULL, 0ULL};
    int k0 = g * 200;
#pragma unroll 4
    for (int kp = k0; kp < k0 + 200; kp++) {
        float v = g_a6[kp * BB + b];
        u64 v2 = pack2(v, v);
#pragma unroll
        for (int c = 0; c < 5; c++) fma2(lg[c], v2, Wp2[kp * 5 + c]);
    }
#pragma unroll
    for (int c = 0; c < 5; c++) {
        float2 f = unpack2(lg[c]);
        red[g][bsub][2 * c] = f.x;
        red[g][bsub][2 * c + 1] = f.y;
    }
    __syncthreads();
    if (g == 0) {
        float logits[10];
#pragma unroll
        for (int c = 0; c < 10; c++)
            logits[c] = red[0][bsub][c] + red[1][bsub][c] + red[2][bsub][c] + red[3][bsub][c] +
                        bfc[c];
        float m = logits[0];
#pragma unroll
        for (int c = 1; c < 10; c++) m = fmaxf(m, logits[c]);
        float s = 0.f;
#pragma unroll
        for (int c = 0; c < 10; c++) {
            float e = expf(logits[c] - m);
            logits[c] = e;
            s += e;
        }
        float inv = 1.f / s;
#pragma unroll
        for (int c = 0; c < 10; c++) out[b * 10 + c] = logits[c] * inv;
    }
}

// ---------------- launch -------------------------------------------------------------------
extern "C" void kernel_launch(void* const* d_in, const int* in_sizes, int n_in, void* d_out,
                              int out_size) {
    const float* x = (const float*)d_in[0];
    const float* K1 = (const float*)d_in[1];
    const float* K2 = (const float*)d_in[2];
    const float* K3 = (const float*)d_in[3];
    const float* K4 = (const float*)d_in[4];
    const float* K5 = (const float*)d_in[5];
    const float* K6 = (const float*)d_in[6];
    const float* Wfc = (const float*)d_in[7];
    const float* bfc = (const float*)d_in[8];
    float* out = (float*)d_out;

    prep_weights<<<4, 512>>>(K2, K3, K4, K5);
    transpose_kernel<<<dim3(74, 256), dim3(32, 8)>>>(x);
    conv1_kernel<<<dim3(128, 13), dim3(32, 3)>>>(K1);
    conv3_mma_kernel<8, 0, 1, 0><<<dim3(128, 144), 128>>>();       // a1   -> ping (K2)
    conv3_mma_kernel<16, 1, 2, 5120><<<dim3(128, 144), 128>>>();   // ping -> pong (K3)
    conv3_mma_kernel<16, 2, 1, 14336><<<dim3(128, 144), 128>>>();  // pong -> ping (K4)
    conv3_mma_kernel<16, 1, 3, 23552><<<dim3(128, 144), 128>>>();  // ping -> bufB fp32 (K5)
    conv6_kernel<<<dim3(128, 5), dim3(32, 8)>>>(K6);               // bufB -> a6
    fc_kernel<<<128, 256>>>(Wfc, bfc, out);
}

// round 15
// speedup vs baseline: 1.3421x; 1.1253x over previous
#include <cuda_runtime.h>
#include <cuda_bf16.h>
#include <math.h>

#define BB 8192

typedef unsigned long long u64;
typedef unsigned int u32;
typedef unsigned short u16;

// ---------------- intermediate buffers (zero-init; halos stay zero = quirk zeros) ----------
__device__ float g_xT[3 * 30 * 30 * BB];  // [c][30][30][b], 28x28 valid at idx 1..28
// bf16 hi/lo activation planes for MMA layers, padded [c][14][14][B]
__device__ u16 g_a1h[8 * 196 * BB], g_a1l[8 * 196 * BB];    // conv1 out
__device__ u16 g_pAh[16 * 196 * BB], g_pAl[16 * 196 * BB];  // ping planes
__device__ u16 g_pBh[16 * 196 * BB], g_pBl[16 * 196 * BB];  // pong planes
__device__ float g_bufB[16 * 196 * BB];                     // K5 out fp32 (for scalar conv6)
__device__ float g_a6[32 * 5 * 5 * BB];                     // layer6 out (compact 5x5)

// pre-packed per-lane mma B-fragments (hi/lo split), one image per conv3 layer:
// layout [kstep][nhalf(2)][plane(2)][lane(32)][2 x u32]
__device__ __align__(16) unsigned char g_wimg[5120 + 3 * 9216 + 64];

// ---------------- f32x2 helpers (scalar layers) --------------------------------------------
__device__ __forceinline__ void fma2(u64& d, u64 a, u64 b) {
    asm("fma.rn.f32x2 %0, %1, %2, %0;" : "+l"(d) : "l"(a), "l"(b));
}
__device__ __forceinline__ u64 pack2(float lo, float hi) {
    u64 r;
    asm("mov.b64 %0, {%1, %2};" : "=l"(r) : "f"(lo), "f"(hi));
    return r;
}
__device__ __forceinline__ float2 unpack2(u64 v) {
    float2 f;
    asm("mov.b64 {%0, %1}, %2;" : "=f"(f.x), "=f"(f.y) : "l"(v));
    return f;
}
__device__ __forceinline__ u64 ldg2(const float* p) {
    return *reinterpret_cast<const u64*>(p);
}

// ---------------- mma / async helpers -------------------------------------------------------
__device__ __forceinline__ void mma16816(float* d, const u32* a, u32 b0, u32 b1) {
    asm volatile(
        "mma.sync.aligned.m16n8k16.row.col.f32.bf16.bf16.f32 "
        "{%0,%1,%2,%3}, {%4,%5,%6,%7}, {%8,%9}, {%0,%1,%2,%3};"
        : "+f"(d[0]), "+f"(d[1]), "+f"(d[2]), "+f"(d[3])
        : "r"(a[0]), "r"(a[1]), "r"(a[2]), "r"(a[3]), "r"(b0), "r"(b1));
}
__device__ __forceinline__ u32 cvt2bf(float h, float l) {
    u32 r;
    asm("cvt.rn.bf16x2.f32 %0, %1, %2;" : "=r"(r) : "f"(h), "f"(l));
    return r;
}
__device__ __forceinline__ u32 smem_to_u32(const void* p) {
    u32 a;
    asm("{ .reg .u64 t; cvta.to.shared.u64 t, %1; cvt.u32.u64 %0, t; }" : "=r"(a) : "l"(p));
    return a;
}
__device__ __forceinline__ void ldm_trans(u32* f, u32 addr) {
    asm volatile(
        "ldmatrix.sync.aligned.m8n8.x4.trans.shared.b16 {%0,%1,%2,%3}, [%4];"
        : "=r"(f[0]), "=r"(f[1]), "=r"(f[2]), "=r"(f[3])
        : "r"(addr));
}
__device__ __forceinline__ void cp16(u32 daddr, const void* src) {
    asm volatile("cp.async.cg.shared.global [%0], [%1], 16;" :: "r"(daddr), "l"(src));
}
#define CP_COMMIT() asm volatile("cp.async.commit_group;" ::: "memory")
#define CP_WAIT1() asm volatile("cp.async.wait_group 1;" ::: "memory")

// ---------------- transpose: x (B, 3*28*28) NCHW -> padded xT [c][30][30][B] ---------------
__global__ void __launch_bounds__(256) transpose_kernel(const float* __restrict__ x) {
    __shared__ float tile[32][33];
    int p0 = blockIdx.x * 32;
    int b0 = blockIdx.y * 32;
    int tx = threadIdx.x, ty = threadIdx.y;  // (32, 8)
#pragma unroll
    for (int j = 0; j < 4; j++) {
        int p = p0 + tx;
        int bb = b0 + ty + 8 * j;
        tile[ty + 8 * j][tx] = (p < 2352) ? x[bb * 2352 + p] : 0.f;
    }
    __syncthreads();
#pragma unroll
    for (int j = 0; j < 4; j++) {
        int p = p0 + ty + 8 * j;
        int bb = b0 + tx;
        if (p < 2352) {
            int c = p / 784, rem = p % 784;
            int h = rem / 28, w = rem % 28;
            g_xT[((c * 30 + h + 1) * 30 + (w + 1)) * BB + bb] = tile[tx][ty + 8 * j];
        }
    }
}

// ---------------- layer 1 (scalar compute; epilogue -> bf16 hi/lo planes) ------------------
template <int OWG>
__device__ __forceinline__ void conv1_body(const u64* __restrict__ ws2, int ow0, int b, int oh) {
    constexpr int S = 2 * OWG + 3;
    u64 acc[8][OWG];
#pragma unroll
    for (int co = 0; co < 8; co++)
#pragma unroll
        for (int ow = 0; ow < OWG; ow++) acc[co][ow] = 0ULL;

#pragma unroll 1
    for (int ci = 0; ci < 3; ci++) {
#pragma unroll
        for (int kh = 0; kh < 5; kh++) {
            const float* rowp = g_xT + ((ci * 30 + 2 * oh + kh) * 30 + 2 * ow0) * BB + b;
            u64 r[S];
#pragma unroll
            for (int j = 0; j < S; j++) r[j] = ldg2(rowp + j * BB);
#pragma unroll
            for (int kw = 0; kw < 5; kw++) {
                int base = ((ci * 5 + kh) * 5 + kw) * 8;
                ulonglong2 w01 = *reinterpret_cast<const ulonglong2*>(ws2 + base);
                ulonglong2 w23 = *reinterpret_cast<const ulonglong2*>(ws2 + base + 2);
                ulonglong2 w45 = *reinterpret_cast<const ulonglong2*>(ws2 + base + 4);
                ulonglong2 w67 = *reinterpret_cast<const ulonglong2*>(ws2 + base + 6);
#pragma unroll
                for (int ow = 0; ow < OWG; ow++) {
                    u64 v = r[2 * ow + kw];
                    fma2(acc[0][ow], v, w01.x);
                    fma2(acc[1][ow], v, w01.y);
                    fma2(acc[2][ow], v, w23.x);
                    fma2(acc[3][ow], v, w23.y);
                    fma2(acc[4][ow], v, w45.x);
                    fma2(acc[5][ow], v, w45.y);
                    fma2(acc[6][ow], v, w67.x);
                    fma2(acc[7][ow], v, w67.y);
                }
            }
        }
    }
#pragma unroll
    for (int co = 0; co < 8; co++)
#pragma unroll
        for (int ow = 0; ow < OWG; ow++) {
            float2 v = unpack2(acc[co][ow]);
            float r0 = fmaxf(v.x, 0.f), r1 = fmaxf(v.y, 0.f);
            u32 hw = cvt2bf(r1, r0);
            float l0 = r0 - __uint_as_float(hw << 16);
            float l1 = r1 - __uint_as_float(hw & 0xffff0000u);
            u32 lw = cvt2bf(l1, l0);
            int idx = (co * 14 + oh + 1) * 14 + ow0 + ow + 1;
            *reinterpret_cast<u32*>(g_a1h + idx * BB + b) = hw;
            *reinterpret_cast<u32*>(g_a1l + idx * BB + b) = lw;
        }
}

__global__ void __launch_bounds__(96) conv1_kernel(const float* __restrict__ Kw) {
    __shared__ __align__(16) u64 ws2[600];
    int tid = threadIdx.y * 32 + threadIdx.x;
    for (int i = tid; i < 600; i += 96) {
        float w = Kw[i];
        ws2[i] = pack2(w, w);
    }
    __syncthreads();
    int b = blockIdx.x * 64 + threadIdx.x * 2;
    int oh = blockIdx.y;
    int ty = threadIdx.y;
    if (ty == 0) conv1_body<4>(ws2, 0, b, oh);
    else if (ty == 1) conv1_body<4>(ws2, 4, b, oh);
    else conv1_body<5>(ws2, 8, b, oh);
}

// ---------------- weight prep: per-lane mma B-fragments, hi/lo bf16 split ------------------
__global__ void __launch_bounds__(512) prep_weights(const float* __restrict__ K2,
                                                    const float* __restrict__ K3,
                                                    const float* __restrict__ K4,
                                                    const float* __restrict__ K5) {
    int l = blockIdx.x;
    const float* W = (l == 0) ? K2 : (l == 1) ? K3 : (l == 2) ? K4 : K5;
    int K = (l == 0) ? 72 : 144;
    int K16 = (l == 0) ? 5 : 9;
    u32* img = reinterpret_cast<u32*>(g_wimg + ((l == 0) ? 0 : 5120 + (l - 1) * 9216));
    int items = K16 * 2 * 2 * 32;  // (s, h, p, lane)
    for (int i = threadIdx.x; i < items; i += 512) {
        int lane = i & 31;
        int p = (i >> 5) & 1;
        int h = (i >> 6) & 1;
        int s = i >> 7;
        int g = lane >> 2, tig = lane & 3;
        int n = h * 8 + g;
        int kk[4] = {s * 16 + tig * 2, s * 16 + tig * 2 + 1, s * 16 + tig * 2 + 8,
                     s * 16 + tig * 2 + 9};
        u16 hs[4];
#pragma unroll
        for (int j = 0; j < 4; j++) {
            float v = (kk[j] < K) ? W[kk[j] * 16 + n] : 0.f;
            __nv_bfloat16 hb = __float2bfloat16(v);
            if (p == 0) {
                hs[j] = __bfloat16_as_ushort(hb);
            } else {
                __nv_bfloat16 lb = __float2bfloat16(v - __bfloat162float(hb));
                hs[j] = __bfloat16_as_ushort(lb);
            }
        }
        img[i * 2] = (u32)hs[0] | ((u32)hs[1] << 16);
        img[i * 2 + 1] = (u32)hs[2] | ((u32)hs[3] << 16);
    }
}

// ---------------- conv3 via mma.sync bf16, cp.async-pipelined A + ldmatrix.trans -----------
// SRC: 0 = a1 planes, 1 = ping planes, 2 = pong planes
// DST: 1 = ping planes, 2 = pong planes, 3 = fp32 g_bufB (for conv6)
template <int CIN, int SRC, int DST, int WOFF>
__global__ void __launch_bounds__(256) conv3_mma_kernel() {
    constexpr int K = CIN * 9;
    constexpr int K16 = (K + 15) / 16;
    constexpr int NFRAG = K16 * 256;  // u32: [s][nh 2][plane 2][lane 32][2]
    constexpr int ROW = 136;          // u16 per k-row (128 + 8 pad) = 272 B
    constexpr int PLANE_U16 = 16 * ROW;

    __shared__ __align__(16) u32 sBF[NFRAG];
    // A tile: [buf 3][plane 2][16 k x ROW] u16
    __shared__ __align__(16) u16 sA[3][2][PLANE_U16];
    __shared__ int koff[K16 * 16];

    const u16* srch = (SRC == 0) ? g_a1h : (SRC == 1) ? g_pAh : g_pBh;
    const u16* srcl = (SRC == 0) ? g_a1l : (SRC == 1) ? g_pAl : g_pBl;

    int tid = threadIdx.x;
    {
        const uint4* src = reinterpret_cast<const uint4*>(g_wimg + WOFF);
        for (int i = tid; i < NFRAG / 4; i += 256)
            reinterpret_cast<uint4*>(sBF)[i] = src[i];
        for (int i = tid; i < K16 * 16; i += 256)
            koff[i] = (i < K) ? ((i / 9) * 196 + ((i % 9) / 3) * 14 + (i % 3)) : 0;
    }

    int lane = tid & 31;
    int w = tid >> 5;  // 0..7
    int tig = lane & 3;
    int g = lane >> 2;
    int bb = blockIdx.x * 128;
    int bw = w * 16;
    int oh = blockIdx.y / 12, ow = blockIdx.y % 12;
    int tap = (oh * 14 + ow) * BB + bb;  // padded top-left tap (u16 index)

    // stage mapping: thread -> (k = tid>>4, x16 = tid&15), both planes
    int sk = tid >> 4, sx = tid & 15;

    // ldmatrix per-lane row address
    int k_l = (lane & 7) + ((lane & 16) >> 1);
    int b_l = bw + (lane & 8);
    u32 sA0 = smem_to_u32(sA);
    u32 lm_byte = (u32)((k_l * ROW + b_l) * 2);

    __syncthreads();  // koff/sBF visible before staging

    auto stage = [&](int s, int bi) {
        int off = koff[s * 16 + sk] * BB + tap + sx * 8;
        u32 d0 = sA0 + (u32)((bi * 2 + 0) * PLANE_U16 + sk * ROW + sx * 8) * 2;
        u32 d1 = sA0 + (u32)((bi * 2 + 1) * PLANE_U16 + sk * ROW + sx * 8) * 2;
        cp16(d0, srch + off);
        cp16(d1, srcl + off);
    };

    float d[2][4] = {{0.f, 0.f, 0.f, 0.f}, {0.f, 0.f, 0.f, 0.f}};

    stage(0, 0);
    CP_COMMIT();
#pragma unroll 1
    for (int s = 0; s < K16; s++) {
        if (s + 1 < K16) stage(s + 1, (s + 1) % 3);
        CP_COMMIT();  // always commit (possibly empty) -> uniform wait depth
        CP_WAIT1();   // group s complete (<=1 newer pending)
        __syncthreads();
        int bi = s % 3;
        u32 ha[4], la[4];
        ldm_trans(ha, sA0 + (u32)((bi * 2 + 0) * PLANE_U16) * 2 + lm_byte);
        ldm_trans(la, sA0 + (u32)((bi * 2 + 1) * PLANE_U16) * 2 + lm_byte);
#pragma unroll
        for (int nh = 0; nh < 2; nh++) {
            const u32* fb = sBF + (((s * 2 + nh) * 2) * 32 + lane) * 2;
            u32 bh0 = fb[0], bh1 = fb[1];    // hi plane
            u32 bl0 = fb[64], bl1 = fb[65];  // lo plane
            mma16816(d[nh], ha, bh0, bh1);   // Ah * Bh
            mma16816(d[nh], la, bh0, bh1);   // Al * Bh
            mma16816(d[nh], ha, bl0, bl1);   // Ah * Bl
        }
    }

    // epilogue: ReLU; write either bf16 hi/lo planes or fp32 (for conv6)
    int obase = ((oh + 1) * 14 + (ow + 1)) * BB + bb + bw;
    if (DST == 3) {
        float* outp = g_bufB + obase;
#pragma unroll
        for (int nh = 0; nh < 2; nh++)
#pragma unroll
            for (int j = 0; j < 4; j++) {
                int co = nh * 8 + tig * 2 + (j & 1);
                int r = g + ((j >> 1) << 3);
                outp[co * 196 * BB + r] = fmaxf(d[nh][j], 0.f);
            }
    } else {
        u16* dh = ((DST == 1) ? g_pAh : g_pBh) + obase;
        u16* dl = ((DST == 1) ? g_pAl : g_pBl) + obase;
#pragma unroll
        for (int nh = 0; nh < 2; nh++)
#pragma unroll
            for (int j = 0; j < 4; j++) {
                int co = nh * 8 + tig * 2 + (j & 1);
                int r = g + ((j >> 1) << 3);
                float rv = fmaxf(d[nh][j], 0.f);
                __nv_bfloat16 hb = __float2bfloat16(rv);
                float lo = rv - __bfloat162float(hb);
                dh[co * 196 * BB + r] = __bfloat16_as_ushort(hb);
                dl[co * 196 * BB + r] = __bfloat16_as_ushort(__float2bfloat16(lo));
            }
    }
}

// ---------------- layer 6 (scalar, reads fp32 g_bufB; from R8) ------------------------------
__global__ void __launch_bounds__(256, 2) conv6_kernel(const float* __restrict__ Kw) {
    __shared__ __align__(16) u64 ws2[3200];
    int tid = threadIdx.y * 32 + threadIdx.x;
    int co0 = threadIdx.y * 4;
    int b = blockIdx.x * 64 + threadIdx.x * 2;
    int oh = blockIdx.y;

    u64 acc[4][5];
#pragma unroll
    for (int co = 0; co < 4; co++)
#pragma unroll
        for (int ow = 0; ow < 5; ow++) acc[co][ow] = 0ULL;

#pragma unroll 1
    for (int cc = 0; cc < 4; cc++) {
        if (cc > 0) __syncthreads();
        for (int i = tid; i < 3200; i += 256) {
            float w = Kw[cc * 3200 + i];
            ws2[i] = pack2(w, w);
        }
        __syncthreads();
#pragma unroll 1
        for (int c4 = 0; c4 < 4; c4++) {
            int ci = cc * 4 + c4;
#pragma unroll
            for (int kh = 0; kh < 5; kh++) {
                const float* rowp = g_bufB + ((ci * 14 + 2 * oh + kh) * 14) * BB + b;
                u64 r[13];
#pragma unroll
                for (int j = 0; j < 13; j++) r[j] = ldg2(rowp + j * BB);
#pragma unroll
                for (int kw = 0; kw < 5; kw++) {
                    int base = (c4 * 25 + kh * 5 + kw) * 32 + co0;
                    ulonglong2 w01 = *reinterpret_cast<const ulonglong2*>(ws2 + base);
                    ulonglong2 w23 = *reinterpret_cast<const ulonglong2*>(ws2 + base + 2);
#pragma unroll
                    for (int ow = 0; ow < 5; ow++) {
                        u64 v = r[2 * ow + kw];
                        fma2(acc[0][ow], v, w01.x);
                        fma2(acc[1][ow], v, w01.y);
                        fma2(acc[2][ow], v, w23.x);
                        fma2(acc[3][ow], v, w23.y);
                    }
                }
            }
        }
    }
#pragma unroll
    for (int co = 0; co < 4; co++)
#pragma unroll
        for (int ow = 0; ow < 5; ow++) {
            float2 v = unpack2(acc[co][ow]);
            *reinterpret_cast<float2*>(g_a6 + (((co0 + co) * 5 + oh) * 5 + ow) * BB + b) = v;
        }
}

// ---------------- FC (1152->10, only 800 nonzero inputs) + softmax -------------------------
__global__ void __launch_bounds__(256) fc_kernel(const float* __restrict__ Wfc,
                                                 const float* __restrict__ bfc,
                                                 float* __restrict__ out) {
    __shared__ __align__(16) float Wp[8000];
    __shared__ float red[4][64][10];
    int tid = threadIdx.x;
    for (int i = tid; i < 8000; i += 256) {
        int kp = i / 10, cls = i % 10;
        int co = kp / 25, rem = kp % 25, r = rem / 5, c = rem % 5;
        Wp[i] = Wfc[cls * 1152 + co * 36 + r * 6 + c];
    }
    __syncthreads();
    const u64* Wp2 = reinterpret_cast<const u64*>(Wp);

    int bsub = tid & 63;
    int g = tid >> 6;
    int b = blockIdx.x * 64 + bsub;

    u64 lg[5] = {0ULL, 0ULL, 0ULL, 0ULL, 0ULL};
    int k0 = g * 200;
#pragma unroll 4
    for (int kp = k0; kp < k0 + 200; kp++) {
        float v = g_a6[kp * BB + b];
        u64 v2 = pack2(v, v);
#pragma unroll
        for (int c = 0; c < 5; c++) fma2(lg[c], v2, Wp2[kp * 5 + c]);
    }
#pragma unroll
    for (int c = 0; c < 5; c++) {
        float2 f = unpack2(lg[c]);
        red[g][bsub][2 * c] = f.x;
        red[g][bsub][2 * c + 1] = f.y;
    }
    __syncthreads();
    if (g == 0) {
        float logits[10];
#pragma unroll
        for (int c = 0; c < 10; c++)
            logits[c] = red[0][bsub][c] + red[1][bsub][c] + red[2][bsub][c] + red[3][bsub][c] +
                        bfc[c];
        float m = logits[0];
#pragma unroll
        for (int c = 1; c < 10; c++) m = fmaxf(m, logits[c]);
        float s = 0.f;
#pragma unroll
        for (int c = 0; c < 10; c++) {
            float e = expf(logits[c] - m);
            logits[c] = e;
            s += e;
        }
        float inv = 1.f / s;
#pragma unroll
        for (int c = 0; c < 10; c++) out[b * 10 + c] = logits[c] * inv;
    }
}

// ---------------- launch -------------------------------------------------------------------
extern "C" void kernel_launch(void* const* d_in, const int* in_sizes, int n_in, void* d_out,
                              int out_size) {
    const float* x = (const float*)d_in[0];
    const float* K1 = (const float*)d_in[1];
    const float* K2 = (const float*)d_in[2];
    const float* K3 = (const float*)d_in[3];
    const float* K4 = (const float*)d_in[4];
    const float* K5 = (const float*)d_in[5];
    const float* K6 = (const float*)d_in[6];
    const float* Wfc = (const float*)d_in[7];
    const float* bfc = (const float*)d_in[8];
    float* out = (float*)d_out;

    prep_weights<<<4, 512>>>(K2, K3, K4, K5);
    transpose_kernel<<<dim3(74, 256), dim3(32, 8)>>>(x);
    conv1_kernel<<<dim3(128, 13), dim3(32, 3)>>>(K1);
    conv3_mma_kernel<8, 0, 1, 0><<<dim3(64, 144), 256>>>();       // a1   -> ping (K2)
    conv3_mma_kernel<16, 1, 2, 5120><<<dim3(64, 144), 256>>>();   // ping -> pong (K3)
    conv3_mma_kernel<16, 2, 1, 14336><<<dim3(64, 144), 256>>>();  // pong -> ping (K4)
    conv3_mma_kernel<16, 1, 3, 23552><<<dim3(64, 144), 256>>>();  // ping -> bufB fp32 (K5)
    conv6_kernel<<<dim3(128, 5), dim3(32, 8)>>>(K6);              // bufB -> a6
    fc_kernel<<<128, 256>>>(Wfc, bfc, out);
}